// round 16
// baseline (speedup 1.0000x reference)
#include <cuda_runtime.h>
#include <cuda_bf16.h>
#include <cuda_fp16.h>
#include <math.h>
#include <stdint.h>
#include <mma.h>

using namespace nvcuda;

// GCN: out = log_softmax( spmm(adj, relu(spmm(adj, x@W1)+b1) @ W2) + b2 )
// R16: ONE change vs R15 (152.5us): support2 stored as fp16 — spmm2's
//      gather halves (102->51MB, 2->1 sectors/edge); array is 3.2MB,
//      fully L2-resident. Everything else identical to R15.

#define MAXN 100000
#define MAXE 1600000
#define SCAN_BLK 256
#define ALDM 36
#define BLDM 68

__device__ int    g_off[MAXN];            // counts -> starts -> ends
__device__ int    g_bsum[1024];           // block sums for scan
__device__ int2   g_csr[MAXE];            // (src, val bits)
__device__ __half g_support1h[(size_t)(MAXN + 128) * 64];  // fp16 support1
__device__ __half g_support2h[(size_t)MAXN * 16];          // fp16 support2

struct __align__(8) half4 { __half2 a, b; };

static __device__ __forceinline__ float cvt_tf32f(float f) {
    uint32_t r;
    asm("cvt.rna.tf32.f32 %0, %1;" : "=r"(r) : "f"(f));
    return __uint_as_float(r);
}

// ---------------------------------------------------------------- CSR build
__global__ void zero_off_kernel(int N) {
    int i = (blockIdx.x * blockDim.x + threadIdx.x) * 4;
    if (i + 4 <= N) {
        *(int4*)&g_off[i] = make_int4(0, 0, 0, 0);
    } else {
        for (int j = i; j < N; j++) g_off[j] = 0;
    }
}

__global__ void hist_kernel(const int* __restrict__ dst, int E) {
    int i = (blockIdx.x * blockDim.x + threadIdx.x) * 4;
    if (i + 4 <= E) {
        int4 d = *(const int4*)(dst + i);
        atomicAdd(&g_off[d.x], 1);
        atomicAdd(&g_off[d.y], 1);
        atomicAdd(&g_off[d.z], 1);
        atomicAdd(&g_off[d.w], 1);
    } else {
        for (int j = i; j < E; j++) atomicAdd(&g_off[dst[j]], 1);
    }
}

__global__ void scan_a_kernel(int N) {
    __shared__ int ws[8];
    int i = blockIdx.x * SCAN_BLK + threadIdx.x;
    int v = (i < N) ? g_off[i] : 0;
    int lane = threadIdx.x & 31, w = threadIdx.x >> 5;
    int s = v;
    #pragma unroll
    for (int d = 16; d > 0; d >>= 1) s += __shfl_xor_sync(0xFFFFFFFFu, s, d);
    if (lane == 0) ws[w] = s;
    __syncthreads();
    if (threadIdx.x == 0) {
        int t = 0;
        #pragma unroll
        for (int k = 0; k < 8; k++) t += ws[k];
        g_bsum[blockIdx.x] = t;
    }
}

__global__ void scan_b_kernel(int nb) {
    __shared__ int wsum[32];
    int t = threadIdx.x;  // 1024
    int v = (t < nb) ? g_bsum[t] : 0;
    int lane = t & 31, w = t >> 5;
    int incl = v;
    #pragma unroll
    for (int d = 1; d < 32; d <<= 1) {
        int n = __shfl_up_sync(0xFFFFFFFFu, incl, d);
        if (lane >= d) incl += n;
    }
    if (lane == 31) wsum[w] = incl;
    __syncthreads();
    if (w == 0) {
        int s = wsum[lane];
        #pragma unroll
        for (int d = 1; d < 32; d <<= 1) {
            int n = __shfl_up_sync(0xFFFFFFFFu, s, d);
            if (lane >= d) s += n;
        }
        wsum[lane] = s;
    }
    __syncthreads();
    int excl = incl - v + (w ? wsum[w - 1] : 0);
    if (t < nb) g_bsum[t] = excl;
}

__global__ void scan_c_kernel(int N) {
    __shared__ int ws[8];
    int i = blockIdx.x * SCAN_BLK + threadIdx.x;
    int v = (i < N) ? g_off[i] : 0;
    int lane = threadIdx.x & 31, w = threadIdx.x >> 5;
    int incl = v;
    #pragma unroll
    for (int d = 1; d < 32; d <<= 1) {
        int n = __shfl_up_sync(0xFFFFFFFFu, incl, d);
        if (lane >= d) incl += n;
    }
    if (lane == 31) ws[w] = incl;
    __syncthreads();
    if (w == 0 && lane < 8) {
        int s = ws[lane];
        #pragma unroll
        for (int d = 1; d < 8; d <<= 1) {
            int n = __shfl_up_sync(0x000000FFu, s, d);
            if (lane >= d) s += n;
        }
        ws[lane] = s;
    }
    __syncthreads();
    int excl = incl - v + (w ? ws[w - 1] : 0);
    if (i < N) g_off[i] = g_bsum[blockIdx.x] + excl;
}

__global__ void scatter_kernel(const int* __restrict__ src,
                               const int* __restrict__ dst,
                               const float* __restrict__ val, int E) {
    int i = (blockIdx.x * blockDim.x + threadIdx.x) * 4;
    if (i + 4 <= E) {
        int4   s = *(const int4*)(src + i);
        int4   d = *(const int4*)(dst + i);
        float4 v = *(const float4*)(val + i);
        int p0 = atomicAdd(&g_off[d.x], 1);
        int p1 = atomicAdd(&g_off[d.y], 1);
        int p2 = atomicAdd(&g_off[d.z], 1);
        int p3 = atomicAdd(&g_off[d.w], 1);
        g_csr[p0] = make_int2(s.x, __float_as_int(v.x));
        g_csr[p1] = make_int2(s.y, __float_as_int(v.y));
        g_csr[p2] = make_int2(s.z, __float_as_int(v.z));
        g_csr[p3] = make_int2(s.w, __float_as_int(v.w));
    } else {
        for (int j = i; j < E; j++) {
            int p = atomicAdd(&g_off[dst[j]], 1);
            g_csr[p] = make_int2(src[j], __float_as_int(val[j]));
        }
    }
}

// ---------------------------------------------------------------- GEMM1 (wmma tf32)
// support1h[N,64] = half( x[N,256] @ W1[256,64] ). R7 mainloop; epilogue
// stages the 128x64 fp32 tile in reused smem and emits half2.
__global__ void __launch_bounds__(128, 3)
gemm1_wmma_kernel(const float* __restrict__ x, const float* __restrict__ W1,
                  int N) {
    __shared__ __align__(16) float sh[8192];  // 32KB: As(18K)+Bs(8.5K) / stage(32K)
    float* As = sh;                  // [128][ALDM]
    float* Bs = sh + 128 * ALDM;     // [32][BLDM]

    int tid = threadIdx.x, wid = tid >> 5;
    int m0 = blockIdx.x * 128;

    wmma::fragment<wmma::accumulator, 16, 16, 8, float> acc[2][4];
    #pragma unroll
    for (int i = 0; i < 2; i++)
        #pragma unroll
        for (int nt = 0; nt < 4; nt++) wmma::fill_fragment(acc[i][nt], 0.0f);

    for (int k0 = 0; k0 < 256; k0 += 32) {
        #pragma unroll
        for (int j = 0; j < 8; j++) {
            int i = tid + (j << 7);            // float4 index
            int row = i >> 3;
            int c4 = (i & 7) << 2;
            int gr = m0 + row;
            float4 v = make_float4(0.f, 0.f, 0.f, 0.f);
            if (gr < N)
                v = *(const float4*)(x + (size_t)gr * 256 + k0 + c4);
            float4 t = make_float4(cvt_tf32f(v.x), cvt_tf32f(v.y),
                                   cvt_tf32f(v.z), cvt_tf32f(v.w));
            *(float4*)&As[row * ALDM + c4] = t;
        }
        #pragma unroll
        for (int j = 0; j < 4; j++) {
            int i = tid + (j << 7);
            int row = i >> 4;
            int c4 = (i & 15) << 2;
            float4 v = *(const float4*)(W1 + (size_t)(k0 + row) * 64 + c4);
            float4 t = make_float4(cvt_tf32f(v.x), cvt_tf32f(v.y),
                                   cvt_tf32f(v.z), cvt_tf32f(v.w));
            *(float4*)&Bs[row * BLDM + c4] = t;
        }
        __syncthreads();

        #pragma unroll
        for (int kk = 0; kk < 4; kk++) {
            wmma::fragment<wmma::matrix_a, 16, 16, 8, wmma::precision::tf32,
                           wmma::row_major> a0, a1;
            wmma::load_matrix_sync(a0, &As[(wid * 32) * ALDM + kk * 8], ALDM);
            wmma::load_matrix_sync(a1, &As[(wid * 32 + 16) * ALDM + kk * 8], ALDM);
            #pragma unroll
            for (int nt = 0; nt < 4; nt++) {
                wmma::fragment<wmma::matrix_b, 16, 16, 8, wmma::precision::tf32,
                               wmma::row_major> b_frag;
                wmma::load_matrix_sync(b_frag, &Bs[(kk * 8) * BLDM + nt * 16], BLDM);
                wmma::mma_sync(acc[0][nt], a0, b_frag, acc[0][nt]);
                wmma::mma_sync(acc[1][nt], a1, b_frag, acc[1][nt]);
            }
        }
        __syncthreads();   // also guards smem reuse below on last iter
    }

    // Epilogue: stage fp32 tile in smem, convert to half2, store.
    #pragma unroll
    for (int i = 0; i < 2; i++)
        #pragma unroll
        for (int nt = 0; nt < 4; nt++)
            wmma::store_matrix_sync(&sh[(wid * 32 + i * 16) * 64 + nt * 16],
                                    acc[i][nt], 64, wmma::mem_row_major);
    __syncthreads();

    // 8192 floats = 4096 float2; 32 per thread
    #pragma unroll
    for (int j = 0; j < 32; j++) {
        int k = tid + (j << 7);       // float2 index
        int row = k >> 5;             // 32 float2 per 64-col row
        int c2 = (k & 31) << 1;       // column (even)
        int gr = m0 + row;
        if (gr < N) {
            float2 v = *(const float2*)&sh[row * 64 + c2];
            *(__half2*)&g_support1h[(size_t)gr * 64 + c2] =
                __floats2half2_rn(v.x, v.y);
        }
    }
}

// ---------------------------------------- spMM1 + (relu,b1) + GEMM2 fused
// 16 threads per node, 4 features each (half4 = 8B loads). x4 unroll.
// Epilogue now emits fp16 support2 (half4 per sub-lane).
__global__ void spmm1_gemm2_kernel(const float* __restrict__ b1,
                                   const float* __restrict__ W2, int N) {
    __shared__ float w2t[16][68];   // transposed W2, padded
    int tid = threadIdx.x;          // 256
    for (int i = tid; i < 64 * 16; i += 256) {
        int k = i >> 4, j = i & 15;
        w2t[j][k] = W2[i];
    }
    __syncthreads();

    int t = blockIdx.x * 256 + tid;
    int node = t >> 4;
    int c = (t & 15) << 2;
    bool valid = (node < N);

    float4 acc = make_float4(0.f, 0.f, 0.f, 0.f);
    if (valid) {
        int start = node ? g_off[node - 1] : 0;
        int end = g_off[node];
        int e = start;
        for (; e + 4 <= end; e += 4) {
            int2 e0 = g_csr[e], e1 = g_csr[e + 1], e2 = g_csr[e + 2], e3 = g_csr[e + 3];
            half4 h0 = *(const half4*)&g_support1h[(size_t)e0.x * 64 + c];
            half4 h1 = *(const half4*)&g_support1h[(size_t)e1.x * 64 + c];
            half4 h2 = *(const half4*)&g_support1h[(size_t)e2.x * 64 + c];
            half4 h3 = *(const half4*)&g_support1h[(size_t)e3.x * 64 + c];
            float w0 = __int_as_float(e0.y), w1 = __int_as_float(e1.y);
            float w2 = __int_as_float(e2.y), w3 = __int_as_float(e3.y);
            float2 l0 = __half22float2(h0.a), u0 = __half22float2(h0.b);
            float2 l1 = __half22float2(h1.a), u1 = __half22float2(h1.b);
            float2 l2 = __half22float2(h2.a), u2 = __half22float2(h2.b);
            float2 l3 = __half22float2(h3.a), u3 = __half22float2(h3.b);
            acc.x = fmaf(w0, l0.x, acc.x); acc.y = fmaf(w0, l0.y, acc.y);
            acc.z = fmaf(w0, u0.x, acc.z); acc.w = fmaf(w0, u0.y, acc.w);
            acc.x = fmaf(w1, l1.x, acc.x); acc.y = fmaf(w1, l1.y, acc.y);
            acc.z = fmaf(w1, u1.x, acc.z); acc.w = fmaf(w1, u1.y, acc.w);
            acc.x = fmaf(w2, l2.x, acc.x); acc.y = fmaf(w2, l2.y, acc.y);
            acc.z = fmaf(w2, u2.x, acc.z); acc.w = fmaf(w2, u2.y, acc.w);
            acc.x = fmaf(w3, l3.x, acc.x); acc.y = fmaf(w3, l3.y, acc.y);
            acc.z = fmaf(w3, u3.x, acc.z); acc.w = fmaf(w3, u3.y, acc.w);
        }
        for (; e < end; e++) {
            int2 ed = g_csr[e];
            float w = __int_as_float(ed.y);
            half4 hv = *(const half4*)&g_support1h[(size_t)ed.x * 64 + c];
            float2 lo = __half22float2(hv.a), hi = __half22float2(hv.b);
            acc.x = fmaf(w, lo.x, acc.x); acc.y = fmaf(w, lo.y, acc.y);
            acc.z = fmaf(w, hi.x, acc.z); acc.w = fmaf(w, hi.y, acc.w);
        }
        float4 bb = *(const float4*)&b1[c];
        acc.x = fmaxf(acc.x + bb.x, 0.f);
        acc.y = fmaxf(acc.y + bb.y, 0.f);
        acc.z = fmaxf(acc.z + bb.z, 0.f);
        acc.w = fmaxf(acc.w + bb.w, 0.f);
    }

    float part[16];
    #pragma unroll
    for (int j = 0; j < 16; j++) {
        float s = acc.x * w2t[j][c];
        s = fmaf(acc.y, w2t[j][c + 1], s);
        s = fmaf(acc.z, w2t[j][c + 2], s);
        s = fmaf(acc.w, w2t[j][c + 3], s);
        part[j] = s;
    }
    #pragma unroll
    for (int d = 1; d < 16; d <<= 1) {
        #pragma unroll
        for (int j = 0; j < 16; j++)
            part[j] += __shfl_xor_sync(0xFFFFFFFFu, part[j], d);
    }
    int sub = t & 15;
    if (valid && sub < 4) {
        half4 hv;
        hv.a = __floats2half2_rn(part[sub * 4], part[sub * 4 + 1]);
        hv.b = __floats2half2_rn(part[sub * 4 + 2], part[sub * 4 + 3]);
        *(half4*)&g_support2h[(size_t)node * 16 + sub * 4] = hv;
    }
}

// ------------------------------------------------ spMM2 + log_softmax fused
// 4 threads per node, 4 classes each as half4 (8B gathers; one 32B sector
// per edge group). x4 unroll, R10 structure.
__global__ void spmm2_kernel(const float* __restrict__ b2,
                             float* __restrict__ out, int N) {
    int t = blockIdx.x * blockDim.x + threadIdx.x;
    int node = t >> 2;
    int q = (t & 3) << 2;

    float4 acc = make_float4(0.f, 0.f, 0.f, 0.f);
    if (node < N) {
        int start = node ? g_off[node - 1] : 0;
        int end = g_off[node];
        int e = start;
        for (; e + 4 <= end; e += 4) {
            int2 e0 = g_csr[e], e1 = g_csr[e + 1], e2 = g_csr[e + 2], e3 = g_csr[e + 3];
            half4 h0 = *(const half4*)&g_support2h[(size_t)e0.x * 16 + q];
            half4 h1 = *(const half4*)&g_support2h[(size_t)e1.x * 16 + q];
            half4 h2 = *(const half4*)&g_support2h[(size_t)e2.x * 16 + q];
            half4 h3 = *(const half4*)&g_support2h[(size_t)e3.x * 16 + q];
            float w0 = __int_as_float(e0.y), w1 = __int_as_float(e1.y);
            float w2 = __int_as_float(e2.y), w3 = __int_as_float(e3.y);
            float2 l0 = __half22float2(h0.a), u0 = __half22float2(h0.b);
            float2 l1 = __half22float2(h1.a), u1 = __half22float2(h1.b);
            float2 l2 = __half22float2(h2.a), u2 = __half22float2(h2.b);
            float2 l3 = __half22float2(h3.a), u3 = __half22float2(h3.b);
            acc.x = fmaf(w0, l0.x, acc.x); acc.y = fmaf(w0, l0.y, acc.y);
            acc.z = fmaf(w0, u0.x, acc.z); acc.w = fmaf(w0, u0.y, acc.w);
            acc.x = fmaf(w1, l1.x, acc.x); acc.y = fmaf(w1, l1.y, acc.y);
            acc.z = fmaf(w1, u1.x, acc.z); acc.w = fmaf(w1, u1.y, acc.w);
            acc.x = fmaf(w2, l2.x, acc.x); acc.y = fmaf(w2, l2.y, acc.y);
            acc.z = fmaf(w2, u2.x, acc.z); acc.w = fmaf(w2, u2.y, acc.w);
            acc.x = fmaf(w3, l3.x, acc.x); acc.y = fmaf(w3, l3.y, acc.y);
            acc.z = fmaf(w3, u3.x, acc.z); acc.w = fmaf(w3, u3.y, acc.w);
        }
        for (; e < end; e++) {
            int2 ed = g_csr[e];
            float w = __int_as_float(ed.y);
            half4 hv = *(const half4*)&g_support2h[(size_t)ed.x * 16 + q];
            float2 lo = __half22float2(hv.a), hi = __half22float2(hv.b);
            acc.x = fmaf(w, lo.x, acc.x); acc.y = fmaf(w, lo.y, acc.y);
            acc.z = fmaf(w, hi.x, acc.z); acc.w = fmaf(w, hi.y, acc.w);
        }
        float4 bb = *(const float4*)&b2[q];
        acc.x += bb.x; acc.y += bb.y; acc.z += bb.z; acc.w += bb.w;
    }

    float m = fmaxf(fmaxf(acc.x, acc.y), fmaxf(acc.z, acc.w));
    m = fmaxf(m, __shfl_xor_sync(0xFFFFFFFFu, m, 1));
    m = fmaxf(m, __shfl_xor_sync(0xFFFFFFFFu, m, 2));
    float s = expf(acc.x - m) + expf(acc.y - m) + expf(acc.z - m) + expf(acc.w - m);
    s += __shfl_xor_sync(0xFFFFFFFFu, s, 1);
    s += __shfl_xor_sync(0xFFFFFFFFu, s, 2);
    float lse = m + logf(s);

    if (node < N) {
        *(float4*)&out[(size_t)node * 16 + q] =
            make_float4(acc.x - lse, acc.y - lse, acc.z - lse, acc.w - lse);
    }
}

// ---------------------------------------------------------------- launch
extern "C" void kernel_launch(void* const* d_in, const int* in_sizes, int n_in,
                              void* d_out, int out_size) {
    const float* x    = (const float*)d_in[0];
    const int*   esrc = (const int*)d_in[1];
    const int*   edst = (const int*)d_in[2];
    const float* ev   = (const float*)d_in[3];
    const float* W1   = (const float*)d_in[4];
    const float* b1   = (const float*)d_in[5];
    const float* W2   = (const float*)d_in[6];
    const float* b2   = (const float*)d_in[7];
    float* out = (float*)d_out;

    int E = in_sizes[1];
    int N = in_sizes[0] / 256;

    int eq = (E + 3) / 4;
    int nq = (N + 3) / 4;
    int nb = (N + SCAN_BLK - 1) / SCAN_BLK;

    // Side stream + events, created once on the first (uncaptured)
    // correctness call; replayed identically under graph capture.
    static cudaStream_t s2 = nullptr;
    static cudaEvent_t evFork = nullptr, evJoin = nullptr;
    if (!s2) {
        cudaStreamCreateWithFlags(&s2, cudaStreamNonBlocking);
        cudaEventCreateWithFlags(&evFork, cudaEventDisableTiming);
        cudaEventCreateWithFlags(&evJoin, cudaEventDisableTiming);
    }

    // Fork: CSR build on s2, gemm1 on the main (capture) stream.
    cudaEventRecord(evFork, 0);
    cudaStreamWaitEvent(s2, evFork, 0);

    zero_off_kernel<<<(nq + 255) / 256, 256, 0, s2>>>(N);          // 0
    hist_kernel<<<(eq + 255) / 256, 256, 0, s2>>>(edst, E);        // 1
    scan_a_kernel<<<nb, SCAN_BLK, 0, s2>>>(N);                     // 2
    gemm1_wmma_kernel<<<(N + 127) / 128, 128>>>(x, W1, N);         // 3 <- profiled
    scan_b_kernel<<<1, 1024, 0, s2>>>(nb);                         // 4
    scan_c_kernel<<<nb, SCAN_BLK, 0, s2>>>(N);                     // 5
    scatter_kernel<<<(eq + 255) / 256, 256, 0, s2>>>(esrc, edst, ev, E);  // 6
    cudaEventRecord(evJoin, s2);

    // Join: spMM needs both gemm1 (program order) and the CSR (event).
    cudaStreamWaitEvent(0, evJoin, 0);

    spmm1_gemm2_kernel<<<(N * 16 + 255) / 256, 256>>>(b1, W2, N);  // 7
    spmm2_kernel<<<(N * 4 + 255) / 256, 256>>>(b2, out, N);        // 8
}

// round 17
// speedup vs baseline: 1.0382x; 1.0382x over previous
#include <cuda_runtime.h>
#include <cuda_bf16.h>
#include <cuda_fp16.h>
#include <math.h>
#include <stdint.h>
#include <mma.h>

using namespace nvcuda;

// GCN: out = log_softmax( spmm(adj, relu(spmm(adj, x@W1)+b1) @ W2) + b2 )
// R17: R15 restored (fp16 support2 of R16 regressed -> reverted; support2
//      back to fp32). ONE change: spmm1 edge loop unrolled x8 — affordable
//      now that gathers are half4 (staging 32 regs vs R11's 48). spmm1 is
//      latency-bound at MLP~4; doubling MLP halves exposed L2 latency.

#define MAXN 100000
#define MAXE 1600000
#define SCAN_BLK 256
#define ALDM 36
#define BLDM 68

__device__ int    g_off[MAXN];            // counts -> starts -> ends
__device__ int    g_bsum[1024];           // block sums for scan
__device__ int2   g_csr[MAXE];            // (src, val bits)
__device__ __half g_support1h[(size_t)(MAXN + 128) * 64];  // fp16 support1
__device__ float  g_support2[(size_t)MAXN * 16];

struct __align__(8) half4 { __half2 a, b; };

static __device__ __forceinline__ float cvt_tf32f(float f) {
    uint32_t r;
    asm("cvt.rna.tf32.f32 %0, %1;" : "=r"(r) : "f"(f));
    return __uint_as_float(r);
}

// ---------------------------------------------------------------- CSR build
__global__ void zero_off_kernel(int N) {
    int i = (blockIdx.x * blockDim.x + threadIdx.x) * 4;
    if (i + 4 <= N) {
        *(int4*)&g_off[i] = make_int4(0, 0, 0, 0);
    } else {
        for (int j = i; j < N; j++) g_off[j] = 0;
    }
}

__global__ void hist_kernel(const int* __restrict__ dst, int E) {
    int i = (blockIdx.x * blockDim.x + threadIdx.x) * 4;
    if (i + 4 <= E) {
        int4 d = *(const int4*)(dst + i);
        atomicAdd(&g_off[d.x], 1);
        atomicAdd(&g_off[d.y], 1);
        atomicAdd(&g_off[d.z], 1);
        atomicAdd(&g_off[d.w], 1);
    } else {
        for (int j = i; j < E; j++) atomicAdd(&g_off[dst[j]], 1);
    }
}

__global__ void scan_a_kernel(int N) {
    __shared__ int ws[8];
    int i = blockIdx.x * SCAN_BLK + threadIdx.x;
    int v = (i < N) ? g_off[i] : 0;
    int lane = threadIdx.x & 31, w = threadIdx.x >> 5;
    int s = v;
    #pragma unroll
    for (int d = 16; d > 0; d >>= 1) s += __shfl_xor_sync(0xFFFFFFFFu, s, d);
    if (lane == 0) ws[w] = s;
    __syncthreads();
    if (threadIdx.x == 0) {
        int t = 0;
        #pragma unroll
        for (int k = 0; k < 8; k++) t += ws[k];
        g_bsum[blockIdx.x] = t;
    }
}

__global__ void scan_b_kernel(int nb) {
    __shared__ int wsum[32];
    int t = threadIdx.x;  // 1024
    int v = (t < nb) ? g_bsum[t] : 0;
    int lane = t & 31, w = t >> 5;
    int incl = v;
    #pragma unroll
    for (int d = 1; d < 32; d <<= 1) {
        int n = __shfl_up_sync(0xFFFFFFFFu, incl, d);
        if (lane >= d) incl += n;
    }
    if (lane == 31) wsum[w] = incl;
    __syncthreads();
    if (w == 0) {
        int s = wsum[lane];
        #pragma unroll
        for (int d = 1; d < 32; d <<= 1) {
            int n = __shfl_up_sync(0xFFFFFFFFu, s, d);
            if (lane >= d) s += n;
        }
        wsum[lane] = s;
    }
    __syncthreads();
    int excl = incl - v + (w ? wsum[w - 1] : 0);
    if (t < nb) g_bsum[t] = excl;
}

__global__ void scan_c_kernel(int N) {
    __shared__ int ws[8];
    int i = blockIdx.x * SCAN_BLK + threadIdx.x;
    int v = (i < N) ? g_off[i] : 0;
    int lane = threadIdx.x & 31, w = threadIdx.x >> 5;
    int incl = v;
    #pragma unroll
    for (int d = 1; d < 32; d <<= 1) {
        int n = __shfl_up_sync(0xFFFFFFFFu, incl, d);
        if (lane >= d) incl += n;
    }
    if (lane == 31) ws[w] = incl;
    __syncthreads();
    if (w == 0 && lane < 8) {
        int s = ws[lane];
        #pragma unroll
        for (int d = 1; d < 8; d <<= 1) {
            int n = __shfl_up_sync(0x000000FFu, s, d);
            if (lane >= d) s += n;
        }
        ws[lane] = s;
    }
    __syncthreads();
    int excl = incl - v + (w ? ws[w - 1] : 0);
    if (i < N) g_off[i] = g_bsum[blockIdx.x] + excl;
}

__global__ void scatter_kernel(const int* __restrict__ src,
                               const int* __restrict__ dst,
                               const float* __restrict__ val, int E) {
    int i = (blockIdx.x * blockDim.x + threadIdx.x) * 4;
    if (i + 4 <= E) {
        int4   s = *(const int4*)(src + i);
        int4   d = *(const int4*)(dst + i);
        float4 v = *(const float4*)(val + i);
        int p0 = atomicAdd(&g_off[d.x], 1);
        int p1 = atomicAdd(&g_off[d.y], 1);
        int p2 = atomicAdd(&g_off[d.z], 1);
        int p3 = atomicAdd(&g_off[d.w], 1);
        g_csr[p0] = make_int2(s.x, __float_as_int(v.x));
        g_csr[p1] = make_int2(s.y, __float_as_int(v.y));
        g_csr[p2] = make_int2(s.z, __float_as_int(v.z));
        g_csr[p3] = make_int2(s.w, __float_as_int(v.w));
    } else {
        for (int j = i; j < E; j++) {
            int p = atomicAdd(&g_off[dst[j]], 1);
            g_csr[p] = make_int2(src[j], __float_as_int(val[j]));
        }
    }
}

// ---------------------------------------------------------------- GEMM1 (wmma tf32)
// support1h[N,64] = half( x[N,256] @ W1[256,64] ). R7 mainloop; epilogue
// stages the 128x64 fp32 tile in reused smem and emits half2.
__global__ void __launch_bounds__(128, 3)
gemm1_wmma_kernel(const float* __restrict__ x, const float* __restrict__ W1,
                  int N) {
    __shared__ __align__(16) float sh[8192];  // 32KB: As(18K)+Bs(8.5K) / stage(32K)
    float* As = sh;                  // [128][ALDM]
    float* Bs = sh + 128 * ALDM;     // [32][BLDM]

    int tid = threadIdx.x, wid = tid >> 5;
    int m0 = blockIdx.x * 128;

    wmma::fragment<wmma::accumulator, 16, 16, 8, float> acc[2][4];
    #pragma unroll
    for (int i = 0; i < 2; i++)
        #pragma unroll
        for (int nt = 0; nt < 4; nt++) wmma::fill_fragment(acc[i][nt], 0.0f);

    for (int k0 = 0; k0 < 256; k0 += 32) {
        #pragma unroll
        for (int j = 0; j < 8; j++) {
            int i = tid + (j << 7);            // float4 index
            int row = i >> 3;
            int c4 = (i & 7) << 2;
            int gr = m0 + row;
            float4 v = make_float4(0.f, 0.f, 0.f, 0.f);
            if (gr < N)
                v = *(const float4*)(x + (size_t)gr * 256 + k0 + c4);
            float4 t = make_float4(cvt_tf32f(v.x), cvt_tf32f(v.y),
                                   cvt_tf32f(v.z), cvt_tf32f(v.w));
            *(float4*)&As[row * ALDM + c4] = t;
        }
        #pragma unroll
        for (int j = 0; j < 4; j++) {
            int i = tid + (j << 7);
            int row = i >> 4;
            int c4 = (i & 15) << 2;
            float4 v = *(const float4*)(W1 + (size_t)(k0 + row) * 64 + c4);
            float4 t = make_float4(cvt_tf32f(v.x), cvt_tf32f(v.y),
                                   cvt_tf32f(v.z), cvt_tf32f(v.w));
            *(float4*)&Bs[row * BLDM + c4] = t;
        }
        __syncthreads();

        #pragma unroll
        for (int kk = 0; kk < 4; kk++) {
            wmma::fragment<wmma::matrix_a, 16, 16, 8, wmma::precision::tf32,
                           wmma::row_major> a0, a1;
            wmma::load_matrix_sync(a0, &As[(wid * 32) * ALDM + kk * 8], ALDM);
            wmma::load_matrix_sync(a1, &As[(wid * 32 + 16) * ALDM + kk * 8], ALDM);
            #pragma unroll
            for (int nt = 0; nt < 4; nt++) {
                wmma::fragment<wmma::matrix_b, 16, 16, 8, wmma::precision::tf32,
                               wmma::row_major> b_frag;
                wmma::load_matrix_sync(b_frag, &Bs[(kk * 8) * BLDM + nt * 16], BLDM);
                wmma::mma_sync(acc[0][nt], a0, b_frag, acc[0][nt]);
                wmma::mma_sync(acc[1][nt], a1, b_frag, acc[1][nt]);
            }
        }
        __syncthreads();   // also guards smem reuse below on last iter
    }

    // Epilogue: stage fp32 tile in smem, convert to half2, store.
    #pragma unroll
    for (int i = 0; i < 2; i++)
        #pragma unroll
        for (int nt = 0; nt < 4; nt++)
            wmma::store_matrix_sync(&sh[(wid * 32 + i * 16) * 64 + nt * 16],
                                    acc[i][nt], 64, wmma::mem_row_major);
    __syncthreads();

    // 8192 floats = 4096 float2; 32 per thread
    #pragma unroll
    for (int j = 0; j < 32; j++) {
        int k = tid + (j << 7);       // float2 index
        int row = k >> 5;             // 32 float2 per 64-col row
        int c2 = (k & 31) << 1;       // column (even)
        int gr = m0 + row;
        if (gr < N) {
            float2 v = *(const float2*)&sh[row * 64 + c2];
            *(__half2*)&g_support1h[(size_t)gr * 64 + c2] =
                __floats2half2_rn(v.x, v.y);
        }
    }
}

// ---------------------------------------- spMM1 + (relu,b1) + GEMM2 fused
// 16 threads per node, 4 features each (half4 = 8B loads). Edge loop
// unrolled x8: staging = 8 int2 + 8 half4 = 32 regs (affordable in fp16).
__global__ void spmm1_gemm2_kernel(const float* __restrict__ b1,
                                   const float* __restrict__ W2, int N) {
    __shared__ float w2t[16][68];   // transposed W2, padded
    int tid = threadIdx.x;          // 256
    for (int i = tid; i < 64 * 16; i += 256) {
        int k = i >> 4, j = i & 15;
        w2t[j][k] = W2[i];
    }
    __syncthreads();

    int t = blockIdx.x * 256 + tid;
    int node = t >> 4;
    int c = (t & 15) << 2;
    bool valid = (node < N);

    float4 acc = make_float4(0.f, 0.f, 0.f, 0.f);
    if (valid) {
        int start = node ? g_off[node - 1] : 0;
        int end = g_off[node];
        int e = start;
        for (; e + 8 <= end; e += 8) {
            int2 ee[8];
            #pragma unroll
            for (int j = 0; j < 8; j++) ee[j] = g_csr[e + j];
            half4 hh[8];
            #pragma unroll
            for (int j = 0; j < 8; j++)
                hh[j] = *(const half4*)&g_support1h[(size_t)ee[j].x * 64 + c];
            #pragma unroll
            for (int j = 0; j < 8; j++) {
                float w = __int_as_float(ee[j].y);
                float2 lo = __half22float2(hh[j].a);
                float2 hi = __half22float2(hh[j].b);
                acc.x = fmaf(w, lo.x, acc.x); acc.y = fmaf(w, lo.y, acc.y);
                acc.z = fmaf(w, hi.x, acc.z); acc.w = fmaf(w, hi.y, acc.w);
            }
        }
        for (; e < end; e++) {
            int2 ed = g_csr[e];
            float w = __int_as_float(ed.y);
            half4 hv = *(const half4*)&g_support1h[(size_t)ed.x * 64 + c];
            float2 lo = __half22float2(hv.a), hi = __half22float2(hv.b);
            acc.x = fmaf(w, lo.x, acc.x); acc.y = fmaf(w, lo.y, acc.y);
            acc.z = fmaf(w, hi.x, acc.z); acc.w = fmaf(w, hi.y, acc.w);
        }
        float4 bb = *(const float4*)&b1[c];
        acc.x = fmaxf(acc.x + bb.x, 0.f);
        acc.y = fmaxf(acc.y + bb.y, 0.f);
        acc.z = fmaxf(acc.z + bb.z, 0.f);
        acc.w = fmaxf(acc.w + bb.w, 0.f);
    }

    float part[16];
    #pragma unroll
    for (int j = 0; j < 16; j++) {
        float s = acc.x * w2t[j][c];
        s = fmaf(acc.y, w2t[j][c + 1], s);
        s = fmaf(acc.z, w2t[j][c + 2], s);
        s = fmaf(acc.w, w2t[j][c + 3], s);
        part[j] = s;
    }
    #pragma unroll
    for (int d = 1; d < 16; d <<= 1) {
        #pragma unroll
        for (int j = 0; j < 16; j++)
            part[j] += __shfl_xor_sync(0xFFFFFFFFu, part[j], d);
    }
    int sub = t & 15;
    if (valid && sub < 4) {
        *(float4*)&g_support2[(size_t)node * 16 + sub * 4] =
            make_float4(part[sub * 4], part[sub * 4 + 1],
                        part[sub * 4 + 2], part[sub * 4 + 3]);
    }
}

// ------------------------------------------------ spMM2 + log_softmax fused
// (R10 version: 4 threads/node, float4 each, x4 unroll; support2 = fp32)
__global__ void spmm2_kernel(const float* __restrict__ b2,
                             float* __restrict__ out, int N) {
    int t = blockIdx.x * blockDim.x + threadIdx.x;
    int node = t >> 2;
    int q = (t & 3) << 2;

    float4 acc = make_float4(0.f, 0.f, 0.f, 0.f);
    if (node < N) {
        int start = node ? g_off[node - 1] : 0;
        int end = g_off[node];
        int e = start;
        for (; e + 4 <= end; e += 4) {
            int2 e0 = g_csr[e], e1 = g_csr[e + 1], e2 = g_csr[e + 2], e3 = g_csr[e + 3];
            float4 v0 = *(const float4*)&g_support2[(size_t)e0.x * 16 + q];
            float4 v1 = *(const float4*)&g_support2[(size_t)e1.x * 16 + q];
            float4 v2 = *(const float4*)&g_support2[(size_t)e2.x * 16 + q];
            float4 v3 = *(const float4*)&g_support2[(size_t)e3.x * 16 + q];
            float w0 = __int_as_float(e0.y), w1 = __int_as_float(e1.y);
            float w2 = __int_as_float(e2.y), w3 = __int_as_float(e3.y);
            acc.x = fmaf(w0, v0.x, acc.x); acc.y = fmaf(w0, v0.y, acc.y);
            acc.z = fmaf(w0, v0.z, acc.z); acc.w = fmaf(w0, v0.w, acc.w);
            acc.x = fmaf(w1, v1.x, acc.x); acc.y = fmaf(w1, v1.y, acc.y);
            acc.z = fmaf(w1, v1.z, acc.z); acc.w = fmaf(w1, v1.w, acc.w);
            acc.x = fmaf(w2, v2.x, acc.x); acc.y = fmaf(w2, v2.y, acc.y);
            acc.z = fmaf(w2, v2.z, acc.z); acc.w = fmaf(w2, v2.w, acc.w);
            acc.x = fmaf(w3, v3.x, acc.x); acc.y = fmaf(w3, v3.y, acc.y);
            acc.z = fmaf(w3, v3.z, acc.z); acc.w = fmaf(w3, v3.w, acc.w);
        }
        for (; e < end; e++) {
            int2 ed = g_csr[e];
            float w = __int_as_float(ed.y);
            float4 v = *(const float4*)&g_support2[(size_t)ed.x * 16 + q];
            acc.x = fmaf(w, v.x, acc.x); acc.y = fmaf(w, v.y, acc.y);
            acc.z = fmaf(w, v.z, acc.z); acc.w = fmaf(w, v.w, acc.w);
        }
        float4 bb = *(const float4*)&b2[q];
        acc.x += bb.x; acc.y += bb.y; acc.z += bb.z; acc.w += bb.w;
    }

    float m = fmaxf(fmaxf(acc.x, acc.y), fmaxf(acc.z, acc.w));
    m = fmaxf(m, __shfl_xor_sync(0xFFFFFFFFu, m, 1));
    m = fmaxf(m, __shfl_xor_sync(0xFFFFFFFFu, m, 2));
    float s = expf(acc.x - m) + expf(acc.y - m) + expf(acc.z - m) + expf(acc.w - m);
    s += __shfl_xor_sync(0xFFFFFFFFu, s, 1);
    s += __shfl_xor_sync(0xFFFFFFFFu, s, 2);
    float lse = m + logf(s);

    if (node < N) {
        *(float4*)&out[(size_t)node * 16 + q] =
            make_float4(acc.x - lse, acc.y - lse, acc.z - lse, acc.w - lse);
    }
}

// ---------------------------------------------------------------- launch
extern "C" void kernel_launch(void* const* d_in, const int* in_sizes, int n_in,
                              void* d_out, int out_size) {
    const float* x    = (const float*)d_in[0];
    const int*   esrc = (const int*)d_in[1];
    const int*   edst = (const int*)d_in[2];
    const float* ev   = (const float*)d_in[3];
    const float* W1   = (const float*)d_in[4];
    const float* b1   = (const float*)d_in[5];
    const float* W2   = (const float*)d_in[6];
    const float* b2   = (const float*)d_in[7];
    float* out = (float*)d_out;

    int E = in_sizes[1];
    int N = in_sizes[0] / 256;

    int eq = (E + 3) / 4;
    int nq = (N + 3) / 4;
    int nb = (N + SCAN_BLK - 1) / SCAN_BLK;

    // Side stream + events, created once on the first (uncaptured)
    // correctness call; replayed identically under graph capture.
    static cudaStream_t s2 = nullptr;
    static cudaEvent_t evFork = nullptr, evJoin = nullptr;
    if (!s2) {
        cudaStreamCreateWithFlags(&s2, cudaStreamNonBlocking);
        cudaEventCreateWithFlags(&evFork, cudaEventDisableTiming);
        cudaEventCreateWithFlags(&evJoin, cudaEventDisableTiming);
    }

    // Fork: CSR build on s2, gemm1 on the main (capture) stream.
    cudaEventRecord(evFork, 0);
    cudaStreamWaitEvent(s2, evFork, 0);

    zero_off_kernel<<<(nq + 255) / 256, 256, 0, s2>>>(N);          // 0
    hist_kernel<<<(eq + 255) / 256, 256, 0, s2>>>(edst, E);        // 1
    scan_a_kernel<<<nb, SCAN_BLK, 0, s2>>>(N);                     // 2
    gemm1_wmma_kernel<<<(N + 127) / 128, 128>>>(x, W1, N);         // 3 <- profiled
    scan_b_kernel<<<1, 1024, 0, s2>>>(nb);                         // 4
    scan_c_kernel<<<nb, SCAN_BLK, 0, s2>>>(N);                     // 5
    scatter_kernel<<<(eq + 255) / 256, 256, 0, s2>>>(esrc, edst, ev, E);  // 6
    cudaEventRecord(evJoin, s2);

    // Join: spMM needs both gemm1 (program order) and the CSR (event).
    cudaStreamWaitEvent(0, evJoin, 0);

    spmm1_gemm2_kernel<<<(N * 16 + 255) / 256, 256>>>(b1, W2, N);  // 7
    spmm2_kernel<<<(N * 4 + 255) / 256, 256>>>(b2, out, N);        // 8
}